// round 8
// baseline (speedup 1.0000x reference)
#include <cuda_runtime.h>
#include <cuda_bf16.h>
#include <math.h>
#include <stdint.h>

#define BATCH   2
#define SEQ     2048
#define DIM     2048
#define HEADS   16
#define HDIM    128
#define SCALE   0.08838834764831845f /* 1/sqrt(128) */

/* ---- scratch (static device arrays; no allocation allowed) ---- */
__device__ float g_q[BATCH*HEADS*SEQ*HDIM];   /* [b][h][s][d] */
__device__ float g_k[BATCH*HEADS*SEQ*HDIM];
__device__ float g_v[BATCH*HEADS*SEQ*HDIM];   /* TRANSPOSED: [b][h][d][s] */
__device__ float g_o[BATCH*SEQ*HEADS*HDIM];   /* [b][s][h*d] */

/* =================== mma.sync helpers (compute_103-safe) =================== */
__device__ __forceinline__ void mma_bf16(float* c, const uint32_t* a, const uint32_t* b) {
    asm volatile("mma.sync.aligned.m16n8k16.row.col.f32.bf16.bf16.f32 "
                 "{%0,%1,%2,%3}, {%4,%5,%6,%7}, {%8,%9}, {%0,%1,%2,%3};"
                 : "+f"(c[0]), "+f"(c[1]), "+f"(c[2]), "+f"(c[3])
                 : "r"(a[0]), "r"(a[1]), "r"(a[2]), "r"(a[3]), "r"(b[0]), "r"(b[1]));
}
__device__ __forceinline__ uint32_t pack_bf16(__nv_bfloat16 lo, __nv_bfloat16 hi) {
    __nv_bfloat162 p = __halves2bfloat162(lo, hi);   /* lo -> .x (low half) */
    return *(uint32_t*)&p;
}

/* ============== bf16x3 GEMM tile machinery (proven round 6) ============== */
#define BUF_STRIDE 32768
#define OFF_ALO    8192
#define OFF_BHI    16384
#define OFF_BLO    24576
#define GEMM_SMEM  65536

__device__ __forceinline__ void fetch_tiles(float4 va[4], float4 vb[4],
                                            const float* __restrict__ A,
                                            const float* __restrict__ B,
                                            int mBase, int nBase, int k0, int tid)
{
    #pragma unroll
    for (int i = 0; i < 4; i++) {
        int f = i * 256 + tid;
        int r = f >> 3, q = f & 7;
        va[i] = *(const float4*)(A + (size_t)(mBase + r) * DIM + k0 + q * 4);
        vb[i] = *(const float4*)(B + (size_t)(nBase + r) * DIM + k0 + q * 4);
    }
}

__device__ __forceinline__ void split_store(const float4 va[4], const float4 vb[4],
                                            char* buf, int tid)
{
    #pragma unroll
    for (int i = 0; i < 4; i++) {
        int f = i * 256 + tid;
        int r = f >> 3, q = f & 7;
        int c0 = q * 4;
        {   /* A element (r, c0..c0+3), fragment-ordered */
            int mt = r >> 4, rr = r & 15, kt = c0 >> 4, cc = c0 & 15;
            int addr = (((mt * 2 + kt) * 32) + ((rr & 7) * 4 + ((cc >> 1) & 3))) * 16
                     + ((rr >> 3) + ((cc >> 3) << 1)) * 4;
            float4 v = va[i];
            __nv_bfloat16 h0 = __float2bfloat16(v.x), h1 = __float2bfloat16(v.y);
            __nv_bfloat16 h2 = __float2bfloat16(v.z), h3 = __float2bfloat16(v.w);
            *(uint32_t*)(buf + addr)      = pack_bf16(h0, h1);
            *(uint32_t*)(buf + addr + 16) = pack_bf16(h2, h3);
            __nv_bfloat16 l0 = __float2bfloat16(v.x - __bfloat162float(h0));
            __nv_bfloat16 l1 = __float2bfloat16(v.y - __bfloat162float(h1));
            __nv_bfloat16 l2 = __float2bfloat16(v.z - __bfloat162float(h2));
            __nv_bfloat16 l3 = __float2bfloat16(v.w - __bfloat162float(h3));
            *(uint32_t*)(buf + OFF_ALO + addr)      = pack_bf16(l0, l1);
            *(uint32_t*)(buf + OFF_ALO + addr + 16) = pack_bf16(l2, l3);
        }
        {   /* B element (n=r, k=c0..c0+3), fragment-ordered */
            int nt = r >> 3, nn = r & 7, kt = c0 >> 4, kk = c0 & 15;
            int addr = (((nt * 2 + kt) * 32) + (nn * 4 + ((kk >> 1) & 3))) * 8
                     + (kk >> 3) * 4;
            float4 v = vb[i];
            __nv_bfloat16 h0 = __float2bfloat16(v.x), h1 = __float2bfloat16(v.y);
            __nv_bfloat16 h2 = __float2bfloat16(v.z), h3 = __float2bfloat16(v.w);
            *(uint32_t*)(buf + OFF_BHI + addr)     = pack_bf16(h0, h1);
            *(uint32_t*)(buf + OFF_BHI + addr + 8) = pack_bf16(h2, h3);
            __nv_bfloat16 l0 = __float2bfloat16(v.x - __bfloat162float(h0));
            __nv_bfloat16 l1 = __float2bfloat16(v.y - __bfloat162float(h1));
            __nv_bfloat16 l2 = __float2bfloat16(v.z - __bfloat162float(h2));
            __nv_bfloat16 l3 = __float2bfloat16(v.w - __bfloat162float(h3));
            *(uint32_t*)(buf + OFF_BLO + addr)     = pack_bf16(l0, l1);
            *(uint32_t*)(buf + OFF_BLO + addr + 8) = pack_bf16(l2, l3);
        }
    }
}

__device__ __forceinline__ void bf16x3_gemm(const float* __restrict__ A,
                                            const float* __restrict__ B,
                                            int mBase, int nBase,
                                            char* smc, float c[2][8][4], int tid)
{
    const int lane = tid & 31, w = tid >> 5, wm = w & 3, wn = w >> 2;

    float4 va[4], vb[4];
    fetch_tiles(va, vb, A, B, mBase, nBase, 0, tid);
    split_store(va, vb, smc, tid);
    __syncthreads();

    for (int ch = 0; ch < 64; ch++) {
        char* cur = smc + (ch & 1) * BUF_STRIDE;
        if (ch < 63)
            fetch_tiles(va, vb, A, B, mBase, nBase, (ch + 1) << 5, tid);

        #pragma unroll
        for (int kt = 0; kt < 2; kt++) {
            uint4 ah[2], al[2];
            #pragma unroll
            for (int m2 = 0; m2 < 2; m2++) {
                int tt = (((wm * 2 + m2) * 2 + kt) * 32 + lane) * 16;
                ah[m2] = *(const uint4*)(cur + tt);
                al[m2] = *(const uint4*)(cur + OFF_ALO + tt);
            }
            #pragma unroll
            for (int n2 = 0; n2 < 8; n2++) {
                int tt = (((wn * 8 + n2) * 2 + kt) * 32 + lane) * 8;
                uint2 bh = *(const uint2*)(cur + OFF_BHI + tt);
                uint2 bl = *(const uint2*)(cur + OFF_BLO + tt);
                #pragma unroll
                for (int m2 = 0; m2 < 2; m2++) {
                    mma_bf16(c[m2][n2], (const uint32_t*)&ah[m2], (const uint32_t*)&bh);
                    mma_bf16(c[m2][n2], (const uint32_t*)&ah[m2], (const uint32_t*)&bl);
                    mma_bf16(c[m2][n2], (const uint32_t*)&al[m2], (const uint32_t*)&bh);
                }
            }
        }

        if (ch < 63)
            split_store(va, vb, smc + ((ch + 1) & 1) * BUF_STRIDE, tid);
        __syncthreads();
    }
}

/* =================== GEMM 1: qkv projection =================== */
__global__ __launch_bounds__(256, 1)
void gemm_qkv_kernel(const float* __restrict__ X, const float* __restrict__ W)
{
    extern __shared__ char smc[];
    const int tid = threadIdx.x;
    const int nTile = blockIdx.x;
    const int mBase = blockIdx.y << 7;
    const int nBase = nTile << 7;

    float c[2][8][4] = {};
    bf16x3_gemm(X, W, mBase, nBase, smc, c, tid);

    const int lane = tid & 31, w = tid >> 5, wm = w & 3, wn = w >> 2;
    const int g = lane >> 2, tig = lane & 3;
    const int which = nTile >> 4;      /* 0=q 1=k 2=v */
    const int head  = nTile & 15;

    if (which == 2) {
        /* V stored TRANSPOSED: g_v[b][h][d][s] */
        #pragma unroll
        for (int m2 = 0; m2 < 2; m2++) {
            int m0 = mBase + wm * 32 + m2 * 16 + g;
            int b0 = m0 >> 11, s0 = m0 & 2047;
            float* vb = g_v + (size_t)(b0 * HEADS + head) * HDIM * SEQ;
            #pragma unroll
            for (int n2 = 0; n2 < 8; n2++) {
                int d = wn * 64 + n2 * 8 + tig * 2;
                vb[(size_t)d * SEQ + s0]           = c[m2][n2][0];
                vb[(size_t)(d + 1) * SEQ + s0]     = c[m2][n2][1];
                vb[(size_t)d * SEQ + s0 + 8]       = c[m2][n2][2];
                vb[(size_t)(d + 1) * SEQ + s0 + 8] = c[m2][n2][3];
            }
        }
    } else {
        float* base = (which == 0) ? g_q : g_k;
        #pragma unroll
        for (int m2 = 0; m2 < 2; m2++) {
            int m0 = mBase + wm * 32 + m2 * 16 + g;
            #pragma unroll
            for (int n2 = 0; n2 < 8; n2++) {
                int d = wn * 64 + n2 * 8 + tig * 2;
                int b0 = m0 >> 11, s0 = m0 & 2047;
                float* p0 = base + ((size_t)((b0 * HEADS + head) * SEQ + s0)) * HDIM + d;
                *(float2*)p0 = make_float2(c[m2][n2][0], c[m2][n2][1]);
                float* p1 = base + ((size_t)((b0 * HEADS + head) * SEQ + s0 + 8)) * HDIM + d;
                *(float2*)p1 = make_float2(c[m2][n2][2], c[m2][n2][3]);
            }
        }
    }
}

/* =================== GEMM 2: output projection =================== */
__global__ __launch_bounds__(256, 1)
void gemm_out_kernel(const float* __restrict__ W, float* __restrict__ Out)
{
    extern __shared__ char smc[];
    const int tid = threadIdx.x;
    const int mBase = blockIdx.y << 7;
    const int nBase = blockIdx.x << 7;

    float c[2][8][4] = {};
    bf16x3_gemm(g_o, W, mBase, nBase, smc, c, tid);

    const int lane = tid & 31, w = tid >> 5, wm = w & 3, wn = w >> 2;
    const int g = lane >> 2, tig = lane & 3;

    #pragma unroll
    for (int m2 = 0; m2 < 2; m2++) {
        int m0 = mBase + wm * 32 + m2 * 16 + g;
        #pragma unroll
        for (int n2 = 0; n2 < 8; n2++) {
            int d = nBase + wn * 64 + n2 * 8 + tig * 2;
            float* p0 = Out + (size_t)m0 * DIM + d;
            *(float2*)p0 = make_float2(c[m2][n2][0], c[m2][n2][1]);
            float* p1 = Out + (size_t)(m0 + 8) * DIM + d;
            *(float2*)p1 = make_float2(c[m2][n2][2], c[m2][n2][3]);
        }
    }
}

/* ===================================================================
 * Flash attention via bf16x3 mma.sync (FA2-style).
 * CTA: 128 q-rows, 8 warps (warp = 16 rows). kv-tile 64.
 * smem: Q A-frags hi/lo (64K), K B-frags hi/lo (32K), V^T B-frags hi/lo (32K)
 * =================================================================== */
#define A_QHI 0
#define A_QLO 32768
#define A_KHI 65536
#define A_KLO 81920
#define A_VHI 98304
#define A_VLO 114688
#define ATTN_SMEM 131072

__global__ __launch_bounds__(256, 1)
void attn_kernel()
{
    extern __shared__ char smc[];
    const int tid  = threadIdx.x;
    const int lane = tid & 31;
    const int w    = tid >> 5;
    const int g    = lane >> 2;
    const int t    = lane & 3;

    const int qBase = blockIdx.x << 7;
    const int bh    = blockIdx.y;
    const float* Qg = g_q + (size_t)bh * SEQ * HDIM;
    const float* Kg = g_k + (size_t)bh * SEQ * HDIM;
    const float* Vt = g_v + (size_t)bh * HDIM * SEQ;   /* [d][s] */

    /* ---- split Q (pre-scaled) into A-fragment smem, once ---- */
    #pragma unroll
    for (int i = 0; i < 16; i++) {
        int f = i * 256 + tid;
        int r = f >> 5, q = f & 31;
        float4 v = *(const float4*)(Qg + (size_t)(qBase + r) * HDIM + q * 4);
        v.x *= SCALE; v.y *= SCALE; v.z *= SCALE; v.w *= SCALE;
        int mt = r >> 4, rr = r & 15, ktd = q >> 2, cc = (q & 3) * 4;
        int addr = ((mt * 8 + ktd) * 32 + (rr & 7) * 4 + ((cc >> 1) & 3)) * 16
                 + ((rr >> 3) + ((cc >> 3) << 1)) * 4;
        __nv_bfloat16 h0 = __float2bfloat16(v.x), h1 = __float2bfloat16(v.y);
        __nv_bfloat16 h2 = __float2bfloat16(v.z), h3 = __float2bfloat16(v.w);
        *(uint32_t*)(smc + A_QHI + addr)      = pack_bf16(h0, h1);
        *(uint32_t*)(smc + A_QHI + addr + 16) = pack_bf16(h2, h3);
        __nv_bfloat16 l0 = __float2bfloat16(v.x - __bfloat162float(h0));
        __nv_bfloat16 l1 = __float2bfloat16(v.y - __bfloat162float(h1));
        __nv_bfloat16 l2 = __float2bfloat16(v.z - __bfloat162float(h2));
        __nv_bfloat16 l3 = __float2bfloat16(v.w - __bfloat162float(h3));
        *(uint32_t*)(smc + A_QLO + addr)      = pack_bf16(l0, l1);
        *(uint32_t*)(smc + A_QLO + addr + 16) = pack_bf16(l2, l3);
    }

    float m0 = -1e30f, m1 = -1e30f, l0r = 0.0f, l1r = 0.0f;
    float o[16][4] = {};

    for (int kv = 0; kv < SEQ / 64; kv++) {
        const int kvBase = kv << 6;

        /* LDG K tile (64x128) and V^T tile (128x64) into registers */
        float4 kst[8], vst[8];
        #pragma unroll
        for (int i = 0; i < 8; i++) {
            int f = i * 256 + tid;
            int r = f >> 5, q = f & 31;
            kst[i] = *(const float4*)(Kg + (size_t)(kvBase + r) * HDIM + q * 4);
        }
        #pragma unroll
        for (int i = 0; i < 8; i++) {
            int f = i * 256 + tid;
            int r = f >> 4, q = f & 15;
            vst[i] = *(const float4*)(Vt + (size_t)r * SEQ + kvBase + q * 4);
        }

        /* split-store K into B-frag smem (n=s_kv, k=d, 8 k-tiles) */
        #pragma unroll
        for (int i = 0; i < 8; i++) {
            int f = i * 256 + tid;
            int r = f >> 5, q = f & 31;
            int nt = r >> 3, nn = r & 7, ktl = q >> 2, kk = (q & 3) * 4;
            int addr = ((nt * 8 + ktl) * 32 + nn * 4 + ((kk >> 1) & 3)) * 8 + (kk >> 3) * 4;
            float4 v = kst[i];
            __nv_bfloat16 h0 = __float2bfloat16(v.x), h1 = __float2bfloat16(v.y);
            __nv_bfloat16 h2 = __float2bfloat16(v.z), h3 = __float2bfloat16(v.w);
            *(uint32_t*)(smc + A_KHI + addr)     = pack_bf16(h0, h1);
            *(uint32_t*)(smc + A_KHI + addr + 8) = pack_bf16(h2, h3);
            __nv_bfloat16 q0 = __float2bfloat16(v.x - __bfloat162float(h0));
            __nv_bfloat16 q1 = __float2bfloat16(v.y - __bfloat162float(h1));
            __nv_bfloat16 q2 = __float2bfloat16(v.z - __bfloat162float(h2));
            __nv_bfloat16 q3 = __float2bfloat16(v.w - __bfloat162float(h3));
            *(uint32_t*)(smc + A_KLO + addr)     = pack_bf16(q0, q1);
            *(uint32_t*)(smc + A_KLO + addr + 8) = pack_bf16(q2, q3);
        }
        __syncthreads();

        /* ---- S = Q K^T (x3) ---- */
        float s[8][4] = {};
        #pragma unroll
        for (int ktd = 0; ktd < 8; ktd++) {
            uint4 ah = *(const uint4*)(smc + A_QHI + ((w * 8 + ktd) * 32 + lane) * 16);
            uint4 al = *(const uint4*)(smc + A_QLO + ((w * 8 + ktd) * 32 + lane) * 16);
            #pragma unroll
            for (int nt = 0; nt < 8; nt++) {
                uint2 kb = *(const uint2*)(smc + A_KHI + ((nt * 8 + ktd) * 32 + lane) * 8);
                uint2 kl = *(const uint2*)(smc + A_KLO + ((nt * 8 + ktd) * 32 + lane) * 8);
                mma_bf16(s[nt], (const uint32_t*)&ah, (const uint32_t*)&kb);
                mma_bf16(s[nt], (const uint32_t*)&ah, (const uint32_t*)&kl);
                mma_bf16(s[nt], (const uint32_t*)&al, (const uint32_t*)&kb);
            }
        }

        /* ---- online softmax on fragments (rows g and g+8) ---- */
        float mx0 = -1e30f, mx1 = -1e30f;
        #pragma unroll
        for (int nt = 0; nt < 8; nt++) {
            mx0 = fmaxf(mx0, fmaxf(s[nt][0], s[nt][1]));
            mx1 = fmaxf(mx1, fmaxf(s[nt][2], s[nt][3]));
        }
        mx0 = fmaxf(mx0, __shfl_xor_sync(0xffffffffu, mx0, 1));
        mx0 = fmaxf(mx0, __shfl_xor_sync(0xffffffffu, mx0, 2));
        mx1 = fmaxf(mx1, __shfl_xor_sync(0xffffffffu, mx1, 1));
        mx1 = fmaxf(mx1, __shfl_xor_sync(0xffffffffu, mx1, 2));
        float nm0 = fmaxf(m0, mx0), nm1 = fmaxf(m1, mx1);
        float a0 = __expf(m0 - nm0), a1 = __expf(m1 - nm1);
        m0 = nm0; m1 = nm1;

        float sum0 = 0.0f, sum1 = 0.0f;
        uint32_t ph[4][4], pl[4][4];
        #pragma unroll
        for (int nt = 0; nt < 8; nt++) {
            float p0 = __expf(s[nt][0] - nm0);
            float p1 = __expf(s[nt][1] - nm0);
            float p2 = __expf(s[nt][2] - nm1);
            float p3 = __expf(s[nt][3] - nm1);
            sum0 += p0 + p1; sum1 += p2 + p3;
            __nv_bfloat16 h0 = __float2bfloat16(p0), h1 = __float2bfloat16(p1);
            __nv_bfloat16 h2 = __float2bfloat16(p2), h3 = __float2bfloat16(p3);
            int ks = nt >> 1, hf = (nt & 1) << 1;
            ph[ks][hf]     = pack_bf16(h0, h1);
            ph[ks][hf + 1] = pack_bf16(h2, h3);
            __nv_bfloat16 e0 = __float2bfloat16(p0 - __bfloat162float(h0));
            __nv_bfloat16 e1 = __float2bfloat16(p1 - __bfloat162float(h1));
            __nv_bfloat16 e2 = __float2bfloat16(p2 - __bfloat162float(h2));
            __nv_bfloat16 e3 = __float2bfloat16(p3 - __bfloat162float(h3));
            pl[ks][hf]     = pack_bf16(e0, e1);
            pl[ks][hf + 1] = pack_bf16(e2, e3);
        }
        sum0 += __shfl_xor_sync(0xffffffffu, sum0, 1);
        sum0 += __shfl_xor_sync(0xffffffffu, sum0, 2);
        sum1 += __shfl_xor_sync(0xffffffffu, sum1, 1);
        sum1 += __shfl_xor_sync(0xffffffffu, sum1, 2);
        l0r = l0r * a0 + sum0;
        l1r = l1r * a1 + sum1;

        /* rescale O */
        #pragma unroll
        for (int nt = 0; nt < 16; nt++) {
            o[nt][0] *= a0; o[nt][1] *= a0;
            o[nt][2] *= a1; o[nt][3] *= a1;
        }

        /* split-store V^T into B-frag smem (n=d, k=s_kv, 4 k-tiles) */
        #pragma unroll
        for (int i = 0; i < 8; i++) {
            int f = i * 256 + tid;
            int r = f >> 4, q = f & 15;
            int nt = r >> 3, nn = r & 7, ktl = q >> 2, kk = (q & 3) * 4;
            int addr = ((nt * 4 + ktl) * 32 + nn * 4 + ((kk >> 1) & 3)) * 8 + (kk >> 3) * 4;
            float4 v = vst[i];
            __nv_bfloat16 h0 = __float2bfloat16(v.x), h1 = __float2bfloat16(v.y);
            __nv_bfloat16 h2 = __float2bfloat16(v.z), h3 = __float2bfloat16(v.w);
            *(uint32_t*)(smc + A_VHI + addr)     = pack_bf16(h0, h1);
            *(uint32_t*)(smc + A_VHI + addr + 8) = pack_bf16(h2, h3);
            __nv_bfloat16 q0 = __float2bfloat16(v.x - __bfloat162float(h0));
            __nv_bfloat16 q1 = __float2bfloat16(v.y - __bfloat162float(h1));
            __nv_bfloat16 q2 = __float2bfloat16(v.z - __bfloat162float(h2));
            __nv_bfloat16 q3 = __float2bfloat16(v.w - __bfloat162float(h3));
            *(uint32_t*)(smc + A_VLO + addr)     = pack_bf16(q0, q1);
            *(uint32_t*)(smc + A_VLO + addr + 8) = pack_bf16(q2, q3);
        }
        __syncthreads();

        /* ---- O += P V (x3) ---- */
        #pragma unroll
        for (int ks = 0; ks < 4; ks++) {
            #pragma unroll
            for (int nt = 0; nt < 16; nt++) {
                uint2 vb = *(const uint2*)(smc + A_VHI + ((nt * 4 + ks) * 32 + lane) * 8);
                uint2 vl = *(const uint2*)(smc + A_VLO + ((nt * 4 + ks) * 32 + lane) * 8);
                mma_bf16(o[nt], ph[ks], (const uint32_t*)&vb);
                mma_bf16(o[nt], ph[ks], (const uint32_t*)&vl);
                mma_bf16(o[nt], pl[ks], (const uint32_t*)&vb);
            }
        }
    }

    /* ---- finalize: O /= l, write g_o[b][s][h*d] ---- */
    float inv0 = 1.0f / l0r, inv1 = 1.0f / l1r;
    int row0 = qBase + w * 16 + g;
    int b = bh >> 4, h = bh & 15;
    float* d0 = g_o + ((size_t)(b * SEQ + row0) * HEADS + h) * HDIM;
    float* d1 = g_o + ((size_t)(b * SEQ + row0 + 8) * HEADS + h) * HDIM;
    #pragma unroll
    for (int nt = 0; nt < 16; nt++) {
        int d = nt * 8 + t * 2;
        *(float2*)(d0 + d) = make_float2(o[nt][0] * inv0, o[nt][1] * inv0);
        *(float2*)(d1 + d) = make_float2(o[nt][2] * inv1, o[nt][3] * inv1);
    }
}

/* =================================================================== */
extern "C" void kernel_launch(void* const* d_in, const int* in_sizes, int n_in,
                              void* d_out, int out_size)
{
    const float* x     = (const float*)d_in[0];
    const float* w_qkv = (const float*)d_in[1];
    const float* w_out = (const float*)d_in[2];
    float* out = (float*)d_out;

    (void)in_sizes; (void)n_in; (void)out_size;

    cudaFuncSetAttribute(gemm_qkv_kernel,
                         cudaFuncAttributeMaxDynamicSharedMemorySize, GEMM_SMEM);
    cudaFuncSetAttribute(gemm_out_kernel,
                         cudaFuncAttributeMaxDynamicSharedMemorySize, GEMM_SMEM);
    cudaFuncSetAttribute(attn_kernel,
                         cudaFuncAttributeMaxDynamicSharedMemorySize, ATTN_SMEM);

    gemm_qkv_kernel<<<dim3(48, 32), 256, GEMM_SMEM>>>(x, w_qkv);
    attn_kernel<<<dim3(SEQ/128, BATCH*HEADS), 256, ATTN_SMEM>>>();
    gemm_out_kernel<<<dim3(16, 32), 256, GEMM_SMEM>>>(w_out, out);
}

// round 11
// speedup vs baseline: 1.0632x; 1.0632x over previous
#include <cuda_runtime.h>
#include <cuda_bf16.h>
#include <math.h>
#include <stdint.h>

#define BATCH   2
#define SEQ     2048
#define DIM     2048
#define HEADS   16
#define HDIM    128
#define SCALE   0.08838834764831845f /* 1/sqrt(128) */

/* ---- scratch (static device arrays; no allocation allowed) ---- */
__device__ float g_q[BATCH*HEADS*SEQ*HDIM];   /* [b][h][s][d] */
__device__ float g_k[BATCH*HEADS*SEQ*HDIM];
__device__ float g_v[BATCH*HEADS*SEQ*HDIM];   /* TRANSPOSED: [b][h][d][s] */

/* pre-split bf16 hi/lo fragment planes (16KB per 128x32 chunk) */
__device__ uint8_t g_xs [32u*64u*16384u];  /* X  A-plane  33.5MB */
__device__ uint8_t g_wqs[48u*64u*16384u];  /* Wqkv B-plane 50MB  */
__device__ uint8_t g_wos[16u*64u*16384u];  /* Wout B-plane 16.8MB*/
__device__ uint8_t g_osp[32u*64u*16384u];  /* O  A-plane  33.5MB */

/* =================== mma.sync helpers (compute_103-safe) =================== */
__device__ __forceinline__ void mma_bf16(float* c, const uint32_t* a, const uint32_t* b) {
    asm volatile("mma.sync.aligned.m16n8k16.row.col.f32.bf16.bf16.f32 "
                 "{%0,%1,%2,%3}, {%4,%5,%6,%7}, {%8,%9}, {%0,%1,%2,%3};"
                 : "+f"(c[0]), "+f"(c[1]), "+f"(c[2]), "+f"(c[3])
                 : "r"(a[0]), "r"(a[1]), "r"(a[2]), "r"(a[3]), "r"(b[0]), "r"(b[1]));
}
__device__ __forceinline__ uint32_t pack_bf16(__nv_bfloat16 lo, __nv_bfloat16 hi) {
    __nv_bfloat162 p = __halves2bfloat162(lo, hi);
    return *(uint32_t*)&p;
}
__device__ __forceinline__ uint32_t smem_u32(const void* p) {
    uint32_t a;
    asm("{ .reg .u64 t; cvta.to.shared.u64 t, %1; cvt.u32.u64 %0, t; }" : "=r"(a) : "l"(p));
    return a;
}
__device__ __forceinline__ void cpa16(uint32_t s, const void* g) {
    asm volatile("cp.async.ca.shared.global [%0], [%1], 16;" :: "r"(s), "l"(g));
}
#define CPA_COMMIT() asm volatile("cp.async.commit_group;" ::: "memory")
#define CPA_WAIT0()  asm volatile("cp.async.wait_group 0;" ::: "memory")

/* ===================================================================
 * Prep kernels: split fp32 -> fragment-ordered, hi/lo-interleaved bf16
 * planes. One CTA per 128x32 chunk (writes 16KB).
 * A-plane word layout: ((mt*2+kt)*32+lane)*32 + sel*16 + p*4
 * B-plane word layout: ((nt*2+kt)*32+lane)*16 + sel*8  + p*4
 * =================================================================== */
__global__ __launch_bounds__(256)
void split_a_kernel(const float* __restrict__ S, uint8_t* __restrict__ D)
{
    const int tid = threadIdx.x;
    const int mBase = blockIdx.y << 7;
    const int k0 = blockIdx.x << 5;
    uint8_t* out = D + ((size_t)blockIdx.y * 64 + blockIdx.x) * 16384;

    #pragma unroll
    for (int i = 0; i < 4; i++) {
        int f = i * 256 + tid;
        int r = f >> 3, c0 = (f & 7) << 2;
        float4 v = *(const float4*)(S + (size_t)(mBase + r) * DIM + k0 + c0);
        int mt = r >> 4, rr = r & 15, kt = c0 >> 4, cc = c0 & 15;
        uint8_t* w = out + (((mt * 2 + kt) * 32 + (rr & 7) * 4 + ((cc >> 1) & 3)) << 5)
                         + (((rr >> 3) + ((cc >> 3) << 1)) << 2);
        __nv_bfloat16 h0 = __float2bfloat16(v.x), h1 = __float2bfloat16(v.y);
        __nv_bfloat16 h2 = __float2bfloat16(v.z), h3 = __float2bfloat16(v.w);
        *(uint32_t*)(w)        = pack_bf16(h0, h1);
        *(uint32_t*)(w + 32)   = pack_bf16(h2, h3);
        *(uint32_t*)(w + 16)   = pack_bf16(__float2bfloat16(v.x - __bfloat162float(h0)),
                                           __float2bfloat16(v.y - __bfloat162float(h1)));
        *(uint32_t*)(w + 48)   = pack_bf16(__float2bfloat16(v.z - __bfloat162float(h2)),
                                           __float2bfloat16(v.w - __bfloat162float(h3)));
    }
}

__global__ __launch_bounds__(256)
void split_b_kernel(const float* __restrict__ S, uint8_t* __restrict__ D)
{
    const int tid = threadIdx.x;
    const int nBase = blockIdx.y << 7;
    const int k0 = blockIdx.x << 5;
    uint8_t* out = D + ((size_t)blockIdx.y * 64 + blockIdx.x) * 16384;

    #pragma unroll
    for (int i = 0; i < 4; i++) {
        int f = i * 256 + tid;
        int r = f >> 3, c0 = (f & 7) << 2;
        float4 v = *(const float4*)(S + (size_t)(nBase + r) * DIM + k0 + c0);
        int nt = r >> 3, nn = r & 7, kt = c0 >> 4, kk = c0 & 15;
        uint8_t* w = out + (((nt * 2 + kt) * 32 + nn * 4 + ((kk >> 1) & 3)) << 4)
                         + ((kk >> 3) << 2);
        __nv_bfloat16 h0 = __float2bfloat16(v.x), h1 = __float2bfloat16(v.y);
        __nv_bfloat16 h2 = __float2bfloat16(v.z), h3 = __float2bfloat16(v.w);
        *(uint32_t*)(w)        = pack_bf16(h0, h1);
        *(uint32_t*)(w + 16)   = pack_bf16(h2, h3);
        *(uint32_t*)(w + 8)    = pack_bf16(__float2bfloat16(v.x - __bfloat162float(h0)),
                                           __float2bfloat16(v.y - __bfloat162float(h1)));
        *(uint32_t*)(w + 24)   = pack_bf16(__float2bfloat16(v.z - __bfloat162float(h2)),
                                           __float2bfloat16(v.w - __bfloat162float(h3)));
    }
}

/* ===================================================================
 * Pre-split bf16x3 GEMM mainloop: cp.async 32KB/chunk -> LDS -> MMA.
 * smem per buffer 32KB (A 16K @0, B 16K @16K), double buffered.
 * =================================================================== */
#define GEMM_SMEM 65536

__device__ __forceinline__ void issue_copy(uint32_t smb, const uint8_t* Ap,
                                           const uint8_t* Bp, int ch, int buf, int tid)
{
    uint32_t sb = smb + buf * 32768 + tid * 16;
    const uint8_t* ga = Ap + (size_t)ch * 16384 + tid * 16;
    const uint8_t* gb = Bp + (size_t)ch * 16384 + tid * 16;
    #pragma unroll
    for (int j = 0; j < 4; j++) cpa16(sb + j * 4096, ga + j * 4096);
    #pragma unroll
    for (int j = 0; j < 4; j++) cpa16(sb + 16384 + j * 4096, gb + j * 4096);
}

__device__ __forceinline__ void mma_mainloop(const uint8_t* __restrict__ Ap,
                                             const uint8_t* __restrict__ Bp,
                                             char* smc, float c[2][8][4], int tid)
{
    const int lane = tid & 31, w = tid >> 5, wm = w & 3, wn = w >> 2;
    const uint32_t smb = smem_u32(smc);

    issue_copy(smb, Ap, Bp, 0, 0, tid);
    CPA_COMMIT();
    CPA_WAIT0();
    __syncthreads();

    for (int ch = 0; ch < 64; ch++) {
        if (ch < 63) { issue_copy(smb, Ap, Bp, ch + 1, (ch + 1) & 1, tid); CPA_COMMIT(); }

        const char* cur = smc + (ch & 1) * 32768;
        #pragma unroll
        for (int kt = 0; kt < 2; kt++) {
            uint4 ah[2], al[2];
            #pragma unroll
            for (int m2 = 0; m2 < 2; m2++) {
                const char* t = cur + (((wm * 2 + m2) * 2 + kt) << 10) + lane * 32;
                ah[m2] = *(const uint4*)(t);
                al[m2] = *(const uint4*)(t + 16);
            }
            #pragma unroll
            for (int n2 = 0; n2 < 8; n2++) {
                uint4 b4 = *(const uint4*)(cur + 16384
                            + ((((wn * 8 + n2) * 2 + kt)) << 9) + lane * 16);
                uint32_t bh[2] = { b4.x, b4.y };
                uint32_t bl[2] = { b4.z, b4.w };
                #pragma unroll
                for (int m2 = 0; m2 < 2; m2++) {
                    mma_bf16(c[m2][n2], (const uint32_t*)&ah[m2], bh);
                    mma_bf16(c[m2][n2], (const uint32_t*)&ah[m2], bl);
                    mma_bf16(c[m2][n2], (const uint32_t*)&al[m2], bh);
                }
            }
        }

        if (ch < 63) CPA_WAIT0();
        __syncthreads();
    }
}

/* =================== GEMM 1: qkv projection =================== */
__global__ __launch_bounds__(256, 2)
void gemm_qkv_kernel()
{
    extern __shared__ char smc[];
    const int tid = threadIdx.x;
    const int nTile = blockIdx.x;
    const int mBlk = blockIdx.y;

    float c[2][8][4] = {};
    mma_mainloop(g_xs + (size_t)mBlk * 64 * 16384,
                 g_wqs + (size_t)nTile * 64 * 16384, smc, c, tid);

    const int lane = tid & 31, w = tid >> 5, wm = w & 3, wn = w >> 2;
    const int g = lane >> 2, tig = lane & 3;
    const int which = nTile >> 4;      /* 0=q 1=k 2=v */
    const int head  = nTile & 15;
    const int mBase = mBlk << 7;

    if (which == 2) {
        /* V stored TRANSPOSED: g_v[b][h][d][s] */
        #pragma unroll
        for (int m2 = 0; m2 < 2; m2++) {
            int m0 = mBase + wm * 32 + m2 * 16 + g;
            int b0 = m0 >> 11, s0 = m0 & 2047;
            float* vb = g_v + (size_t)(b0 * HEADS + head) * HDIM * SEQ;
            #pragma unroll
            for (int n2 = 0; n2 < 8; n2++) {
                int d = wn * 64 + n2 * 8 + tig * 2;
                vb[(size_t)d * SEQ + s0]           = c[m2][n2][0];
                vb[(size_t)(d + 1) * SEQ + s0]     = c[m2][n2][1];
                vb[(size_t)d * SEQ + s0 + 8]       = c[m2][n2][2];
                vb[(size_t)(d + 1) * SEQ + s0 + 8] = c[m2][n2][3];
            }
        }
    } else {
        float* base = (which == 0) ? g_q : g_k;
        #pragma unroll
        for (int m2 = 0; m2 < 2; m2++) {
            int m0 = mBase + wm * 32 + m2 * 16 + g;
            #pragma unroll
            for (int n2 = 0; n2 < 8; n2++) {
                int d = wn * 64 + n2 * 8 + tig * 2;
                int b0 = m0 >> 11, s0 = m0 & 2047;
                float* p0 = base + ((size_t)((b0 * HEADS + head) * SEQ + s0)) * HDIM + d;
                *(float2*)p0 = make_float2(c[m2][n2][0], c[m2][n2][1]);
                float* p1 = base + ((size_t)((b0 * HEADS + head) * SEQ + s0 + 8)) * HDIM + d;
                *(float2*)p1 = make_float2(c[m2][n2][2], c[m2][n2][3]);
            }
        }
    }
}

/* =================== GEMM 2: output projection =================== */
__global__ __launch_bounds__(256, 2)
void gemm_out_kernel(float* __restrict__ Out)
{
    extern __shared__ char smc[];
    const int tid = threadIdx.x;
    const int mBlk = blockIdx.y;
    const int nBase = blockIdx.x << 7;

    float c[2][8][4] = {};
    mma_mainloop(g_osp + (size_t)mBlk * 64 * 16384,
                 g_wos + (size_t)blockIdx.x * 64 * 16384, smc, c, tid);

    const int lane = tid & 31, w = tid >> 5, wm = w & 3, wn = w >> 2;
    const int g = lane >> 2, tig = lane & 3;
    const int mBase = mBlk << 7;

    #pragma unroll
    for (int m2 = 0; m2 < 2; m2++) {
        int m0 = mBase + wm * 32 + m2 * 16 + g;
        #pragma unroll
        for (int n2 = 0; n2 < 8; n2++) {
            int d = nBase + wn * 64 + n2 * 8 + tig * 2;
            float* p0 = Out + (size_t)m0 * DIM + d;
            *(float2*)p0 = make_float2(c[m2][n2][0], c[m2][n2][1]);
            float* p1 = Out + (size_t)(m0 + 8) * DIM + d;
            *(float2*)p1 = make_float2(c[m2][n2][2], c[m2][n2][3]);
        }
    }
}

/* ===================================================================
 * Flash attention via bf16x3 mma.sync (round-8 mainloop, unchanged).
 * Epilogue now writes O as a pre-split A-plane for gemm_out.
 * =================================================================== */
#define A_QHI 0
#define A_QLO 32768
#define A_KHI 65536
#define A_KLO 81920
#define A_VHI 98304
#define A_VLO 114688
#define ATTN_SMEM 131072

__global__ __launch_bounds__(256, 1)
void attn_kernel()
{
    extern __shared__ char smc[];
    const int tid  = threadIdx.x;
    const int lane = tid & 31;
    const int w    = tid >> 5;
    const int g    = lane >> 2;
    const int t    = lane & 3;

    const int qBase = blockIdx.x << 7;
    const int bh    = blockIdx.y;
    const float* Qg = g_q + (size_t)bh * SEQ * HDIM;
    const float* Kg = g_k + (size_t)bh * SEQ * HDIM;
    const float* Vt = g_v + (size_t)bh * HDIM * SEQ;   /* [d][s] */

    /* ---- split Q (pre-scaled) into A-fragment smem, once ---- */
    #pragma unroll
    for (int i = 0; i < 16; i++) {
        int f = i * 256 + tid;
        int r = f >> 5, q = f & 31;
        float4 v = *(const float4*)(Qg + (size_t)(qBase + r) * HDIM + q * 4);
        v.x *= SCALE; v.y *= SCALE; v.z *= SCALE; v.w *= SCALE;
        int mt = r >> 4, rr = r & 15, ktd = q >> 2, cc = (q & 3) * 4;
        int addr = ((mt * 8 + ktd) * 32 + (rr & 7) * 4 + ((cc >> 1) & 3)) * 16
                 + ((rr >> 3) + ((cc >> 3) << 1)) * 4;
        __nv_bfloat16 h0 = __float2bfloat16(v.x), h1 = __float2bfloat16(v.y);
        __nv_bfloat16 h2 = __float2bfloat16(v.z), h3 = __float2bfloat16(v.w);
        *(uint32_t*)(smc + A_QHI + addr)      = pack_bf16(h0, h1);
        *(uint32_t*)(smc + A_QHI + addr + 16) = pack_bf16(h2, h3);
        __nv_bfloat16 l0 = __float2bfloat16(v.x - __bfloat162float(h0));
        __nv_bfloat16 l1 = __float2bfloat16(v.y - __bfloat162float(h1));
        __nv_bfloat16 l2 = __float2bfloat16(v.z - __bfloat162float(h2));
        __nv_bfloat16 l3 = __float2bfloat16(v.w - __bfloat162float(h3));
        *(uint32_t*)(smc + A_QLO + addr)      = pack_bf16(l0, l1);
        *(uint32_t*)(smc + A_QLO + addr + 16) = pack_bf16(l2, l3);
    }

    float m0 = -1e30f, m1 = -1e30f, l0r = 0.0f, l1r = 0.0f;
    float o[16][4] = {};

    for (int kv = 0; kv < SEQ / 64; kv++) {
        const int kvBase = kv << 6;

        float4 kst[8], vst[8];
        #pragma unroll
        for (int i = 0; i < 8; i++) {
            int f = i * 256 + tid;
            int r = f >> 5, q = f & 31;
            kst[i] = *(const float4*)(Kg + (size_t)(kvBase + r) * HDIM + q * 4);
        }
        #pragma unroll
        for (int i = 0; i < 8; i++) {
            int f = i * 256 + tid;
            int r = f >> 4, q = f & 15;
            vst[i] = *(const float4*)(Vt + (size_t)r * SEQ + kvBase + q * 4);
        }

        #pragma unroll
        for (int i = 0; i < 8; i++) {
            int f = i * 256 + tid;
            int r = f >> 5, q = f & 31;
            int nt = r >> 3, nn = r & 7, ktl = q >> 2, kk = (q & 3) * 4;
            int addr = ((nt * 8 + ktl) * 32 + nn * 4 + ((kk >> 1) & 3)) * 8 + (kk >> 3) * 4;
            float4 v = kst[i];
            __nv_bfloat16 h0 = __float2bfloat16(v.x), h1 = __float2bfloat16(v.y);
            __nv_bfloat16 h2 = __float2bfloat16(v.z), h3 = __float2bfloat16(v.w);
            *(uint32_t*)(smc + A_KHI + addr)     = pack_bf16(h0, h1);
            *(uint32_t*)(smc + A_KHI + addr + 8) = pack_bf16(h2, h3);
            __nv_bfloat16 q0 = __float2bfloat16(v.x - __bfloat162float(h0));
            __nv_bfloat16 q1 = __float2bfloat16(v.y - __bfloat162float(h1));
            __nv_bfloat16 q2 = __float2bfloat16(v.z - __bfloat162float(h2));
            __nv_bfloat16 q3 = __float2bfloat16(v.w - __bfloat162float(h3));
            *(uint32_t*)(smc + A_KLO + addr)     = pack_bf16(q0, q1);
            *(uint32_t*)(smc + A_KLO + addr + 8) = pack_bf16(q2, q3);
        }
        __syncthreads();

        float s[8][4] = {};
        #pragma unroll
        for (int ktd = 0; ktd < 8; ktd++) {
            uint4 ah = *(const uint4*)(smc + A_QHI + ((w * 8 + ktd) * 32 + lane) * 16);
            uint4 al = *(const uint4*)(smc + A_QLO + ((w * 8 + ktd) * 32 + lane) * 16);
            #pragma unroll
            for (int nt = 0; nt < 8; nt++) {
                uint2 kb = *(const uint2*)(smc + A_KHI + ((nt * 8 + ktd) * 32 + lane) * 8);
                uint2 kl = *(const uint2*)(smc + A_KLO + ((nt * 8 + ktd) * 32 + lane) * 8);
                mma_bf16(s[nt], (const uint32_t*)&ah, (const uint32_t*)&kb);
                mma_bf16(s[nt], (const uint32_t*)&ah, (const uint32_t*)&kl);
                mma_bf16(s[nt], (const uint32_t*)&al, (const uint32_t*)&kb);
            }
        }

        float mx0 = -1e30f, mx1 = -1e30f;
        #pragma unroll
        for (int nt = 0; nt < 8; nt++) {
            mx0 = fmaxf(mx0, fmaxf(s[nt][0], s[nt][1]));
            mx1 = fmaxf(mx1, fmaxf(s[nt][2], s[nt][3]));
        }
        mx0 = fmaxf(mx0, __shfl_xor_sync(0xffffffffu, mx0, 1));
        mx0 = fmaxf(mx0, __shfl_xor_sync(0xffffffffu, mx0, 2));
        mx1 = fmaxf(mx1, __shfl_xor_sync(0xffffffffu, mx1, 1));
        mx1 = fmaxf(mx1, __shfl_xor_sync(0xffffffffu, mx1, 2));
        float nm0 = fmaxf(m0, mx0), nm1 = fmaxf(m1, mx1);
        float a0 = __expf(m0 - nm0), a1 = __expf(m1 - nm1);
        m0 = nm0; m1 = nm1;

        float sum0 = 0.0f, sum1 = 0.0f;
        uint32_t ph[4][4], pl[4][4];
        #pragma unroll
        for (int nt = 0; nt < 8; nt++) {
            float p0 = __expf(s[nt][0] - nm0);
            float p1 = __expf(s[nt][1] - nm0);
            float p2 = __expf(s[nt][2] - nm1);
            float p3 = __expf(s[nt][3] - nm1);
            sum0 += p0 + p1; sum1 += p2 + p3;
            __nv_bfloat16 h0 = __float2bfloat16(p0), h1 = __float2bfloat16(p1);
            __nv_bfloat16 h2 = __float2bfloat16(p2), h3 = __float2bfloat16(p3);
            int ks = nt >> 1, hf = (nt & 1) << 1;
            ph[ks][hf]     = pack_bf16(h0, h1);
            ph[ks][hf + 1] = pack_bf16(h2, h3);
            __nv_bfloat16 e0 = __float2bfloat16(p0 - __bfloat162float(h0));
            __nv_bfloat16 e1 = __float2bfloat16(p1 - __bfloat162float(h1));
            __nv_bfloat16 e2 = __float2bfloat16(p2 - __bfloat162float(h2));
            __nv_bfloat16 e3 = __float2bfloat16(p3 - __bfloat162float(h3));
            pl[ks][hf]     = pack_bf16(e0, e1);
            pl[ks][hf + 1] = pack_bf16(e2, e3);
        }
        sum0 += __shfl_xor_sync(0xffffffffu, sum0, 1);
        sum0 += __shfl_xor_sync(0xffffffffu, sum0, 2);
        sum1 += __shfl_xor_sync(0xffffffffu, sum1, 1);
        sum1 += __shfl_xor_sync(0xffffffffu, sum1, 2);
        l0r = l0r * a0 + sum0;
        l1r = l1r * a1 + sum1;

        #pragma unroll
        for (int nt = 0; nt < 16; nt++) {
            o[nt][0] *= a0; o[nt][1] *= a0;
            o[nt][2] *= a1; o[nt][3] *= a1;
        }

        #pragma unroll
        for (int i = 0; i < 8; i++) {
            int f = i * 256 + tid;
            int r = f >> 4, q = f & 15;
            int nt = r >> 3, nn = r & 7, ktl = q >> 2, kk = (q & 3) * 4;
            int addr = ((nt * 4 + ktl) * 32 + nn * 4 + ((kk >> 1) & 3)) * 8 + (kk >> 3) * 4;
            float4 v = vst[i];
            __nv_bfloat16 h0 = __float2bfloat16(v.x), h1 = __float2bfloat16(v.y);
            __nv_bfloat16 h2 = __float2bfloat16(v.z), h3 = __float2bfloat16(v.w);
            *(uint32_t*)(smc + A_VHI + addr)     = pack_bf16(h0, h1);
            *(uint32_t*)(smc + A_VHI + addr + 8) = pack_bf16(h2, h3);
            __nv_bfloat16 q0 = __float2bfloat16(v.x - __bfloat162float(h0));
            __nv_bfloat16 q1 = __float2bfloat16(v.y - __bfloat162float(h1));
            __nv_bfloat16 q2 = __float2bfloat16(v.z - __bfloat162float(h2));
            __nv_bfloat16 q3 = __float2bfloat16(v.w - __bfloat162float(h3));
            *(uint32_t*)(smc + A_VLO + addr)     = pack_bf16(q0, q1);
            *(uint32_t*)(smc + A_VLO + addr + 8) = pack_bf16(q2, q3);
        }
        __syncthreads();

        #pragma unroll
        for (int ks = 0; ks < 4; ks++) {
            #pragma unroll
            for (int nt = 0; nt < 16; nt++) {
                uint2 vb = *(const uint2*)(smc + A_VHI + ((nt * 4 + ks) * 32 + lane) * 8);
                uint2 vl = *(const uint2*)(smc + A_VLO + ((nt * 4 + ks) * 32 + lane) * 8);
                mma_bf16(o[nt], ph[ks], (const uint32_t*)&vb);
                mma_bf16(o[nt], ph[ks], (const uint32_t*)&vl);
                mma_bf16(o[nt], pl[ks], (const uint32_t*)&vb);
            }
        }
    }

    /* ---- finalize: O /= l, write pre-split A-plane for gemm_out ---- */
    float inv0 = 1.0f / l0r, inv1 = 1.0f / l1r;
    const int b = bh >> 4, h = bh & 15;
    const int mBlk = (b * SEQ + qBase) >> 7;   /* qBase is 128-aligned */
    #pragma unroll
    for (int nt = 0; nt < 16; nt++) {
        int d_total = h * 128 + nt * 8 + t * 2;
        int ch = d_total >> 5;
        int kt = (d_total >> 4) & 1;
        int p  = ((d_total >> 3) & 1) << 1;
        uint8_t* base = g_osp + ((size_t)(mBlk * 64 + ch) << 14)
                      + (((w * 2 + kt) * 32 + lane) << 5);
        float v0 = o[nt][0] * inv0, v1 = o[nt][1] * inv0;
        float v2 = o[nt][2] * inv1, v3 = o[nt][3] * inv1;
        __nv_bfloat16 h0 = __float2bfloat16(v0), h1 = __float2bfloat16(v1);
        __nv_bfloat16 h2 = __float2bfloat16(v2), h3 = __float2bfloat16(v3);
        *(uint32_t*)(base + p * 4)            = pack_bf16(h0, h1);        /* row g   hi */
        *(uint32_t*)(base + (p + 1) * 4)      = pack_bf16(h2, h3);        /* row g+8 hi */
        *(uint32_t*)(base + 16 + p * 4)       = pack_bf16(
            __float2bfloat16(v0 - __bfloat162float(h0)),
            __float2bfloat16(v1 - __bfloat162float(h1)));
        *(uint32_t*)(base + 16 + (p + 1) * 4) = pack_bf16(
            __float2bfloat16(v2 - __bfloat162float(h2)),
            __float2bfloat16(v3 - __bfloat162float(h3)));
    }
}

/* =================================================================== */
extern "C" void kernel_launch(void* const* d_in, const int* in_sizes, int n_in,
                              void* d_out, int out_size)
{
    const float* x     = (const float*)d_in[0];
    const float* w_qkv = (const float*)d_in[1];
    const float* w_out = (const float*)d_in[2];
    float* out = (float*)d_out;

    (void)in_sizes; (void)n_in; (void)out_size;

    cudaFuncSetAttribute(gemm_qkv_kernel,
                         cudaFuncAttributeMaxDynamicSharedMemorySize, GEMM_SMEM);
    cudaFuncSetAttribute(gemm_out_kernel,
                         cudaFuncAttributeMaxDynamicSharedMemorySize, GEMM_SMEM);
    cudaFuncSetAttribute(attn_kernel,
                         cudaFuncAttributeMaxDynamicSharedMemorySize, ATTN_SMEM);

    uint8_t* p_xs;  cudaGetSymbolAddress((void**)&p_xs,  g_xs);
    uint8_t* p_wqs; cudaGetSymbolAddress((void**)&p_wqs, g_wqs);
    uint8_t* p_wos; cudaGetSymbolAddress((void**)&p_wos, g_wos);

    split_a_kernel<<<dim3(64, 32), 256>>>(x, p_xs);
    split_b_kernel<<<dim3(64, 48), 256>>>(w_qkv, p_wqs);
    split_b_kernel<<<dim3(64, 16), 256>>>(w_out, p_wos);

    gemm_qkv_kernel<<<dim3(48, 32), 256, GEMM_SMEM>>>();
    attn_kernel<<<dim3(SEQ/128, BATCH*HEADS), 256, ATTN_SMEM>>>();
    gemm_out_kernel<<<dim3(16, 32), 256, GEMM_SMEM>>>(out);
}